// round 13
// baseline (speedup 1.0000x reference)
#include <cuda_runtime.h>
#include <cstdint>

// Problem constants
#define S_LEN   64
#define D_MODEL 768
#define D_FFN   3072
#define RANK    16
#define MOD_SCALE 0.1f

// Packed f32x2 FMA (ptxas won't auto-fuse from C++).
#define FMA_F32X2(d, a, b, c) \
    asm("fma.rn.f32x2 %0, %1, %2, %3;" : "=l"(d) : "l"(a), "l"(b), "l"(c))
// Pack two scalars into a 64-bit f32x2 operand.
#define PACK_F32X2(d, lo, hi) \
    asm("mov.b64 %0, {%1, %2};" : "=l"(d) : "r"(__float_as_uint(lo)), "r"(__float_as_uint(hi)))

// Scratch: modulation (64 x 16) + work-stealing counter. Device globals.
__device__ float    g_mod[S_LEN * RANK];
__device__ unsigned g_ctr;

// ---------------------------------------------------------------------------
// Kernel 1: modulation[s][r] = 0.1 * tanh( sum_d attn[s][d] * A[d][r] )
// Warp-per-output; also resets the work counter for the deltaw launch.
// ---------------------------------------------------------------------------
__global__ __launch_bounds__(256)
void mod_kernel(const float* __restrict__ attn,
                const float* __restrict__ A)
{
    if (blockIdx.x == 0 && threadIdx.x == 0) g_ctr = 0u;

    const int gw  = blockIdx.x * 8 + (threadIdx.x >> 5);  // 0..1023
    const int lid = threadIdx.x & 31;
    const int s   = gw >> 4;
    const int r   = gw & 15;

    const float* arow = attn + (size_t)s * D_MODEL;
    float acc = 0.0f;
#pragma unroll
    for (int k = 0; k < D_MODEL / 32; k++) {              // 24 iterations
        const int d = lid + 32 * k;
        acc += arow[d] * A[d * RANK + r];
    }
#pragma unroll
    for (int off = 16; off > 0; off >>= 1)
        acc += __shfl_down_sync(0xFFFFFFFFu, acc, off);

    if (lid == 0) g_mod[s * RANK + r] = MOD_SCALE * tanhf(acc);
}

// ---------------------------------------------------------------------------
// Kernel 2: delta_w[p][f] = sum_r C[p][r] * B[r][f]
//
// R-PACKED f32x2 formulation: the two f32x2 lanes carry consecutive r values
// (not consecutive f), so the packed C operand {c[2j], c[2j+1]} comes
// STRAIGHT from LDS.128 of the C row — the 16 mov.b64 duplications per pair
// are gone. B is pre-interleaved once per f-tile:
//     Bp[j][f] = { B[2j][f], B[2j+1][f] }   (64 regs, same as before)
// Per pair per thread: 4x LDS.128 + 32 FFMA2 (4 chains x 8 deep) +
// 4 horizontal adds + 1 streaming STG.128.
// Scheduler: persistent 444 blocks, work-steal with claim-ahead (R9).
// ---------------------------------------------------------------------------
#define FTILE        1024
#define CHUNK_PAIRS  64
#define THREADS      256
#define N_PCHUNK     ((S_LEN * D_MODEL) / CHUNK_PAIRS)    // 768
#define N_ITEMS      (N_PCHUNK * (D_FFN / FTILE))         // 2304
#define GRID_BLOCKS  444

__global__ __launch_bounds__(THREADS, 3)
void deltaw_kernel(const float* __restrict__ A,
                   const float* __restrict__ B,
                   float* __restrict__ out)
{
    __shared__ __align__(16) float Cs[CHUNK_PAIRS][RANK];
    __shared__ unsigned s_claim;

    uint64_t Bp[8][4];     // Bp[j][f] = {B[2j][f0+f], B[2j+1][f0+f]}
    int prev_ftile = -1;

    if (threadIdx.x == 0) s_claim = atomicAdd(&g_ctr, 1u);
    __syncthreads();

    for (;;) {
        const unsigned idx = s_claim;
        if (idx >= N_ITEMS) break;

        // Claim-ahead: issue next atomic now, publish after compute.
        unsigned next_claim = 0u;
        if (threadIdx.x == 0) next_claim = atomicAdd(&g_ctr, 1u);

        const int ftile = (int)(idx / N_PCHUNK);          // 0..2
        const int pair0 = (int)(idx % N_PCHUNK) * CHUNK_PAIRS;
        const int f0    = ftile * FTILE + threadIdx.x * 4;

        // Interleave B rows 2j / 2j+1 into packed registers (tile change only).
        if (ftile != prev_ftile) {
            prev_ftile = ftile;
#pragma unroll
            for (int j = 0; j < 8; j++) {
                const float4 lo = *reinterpret_cast<const float4*>(&B[(2 * j)     * D_FFN + f0]);
                const float4 hi = *reinterpret_cast<const float4*>(&B[(2 * j + 1) * D_FFN + f0]);
                PACK_F32X2(Bp[j][0], lo.x, hi.x);
                PACK_F32X2(Bp[j][1], lo.y, hi.y);
                PACK_F32X2(Bp[j][2], lo.z, hi.z);
                PACK_F32X2(Bp[j][3], lo.w, hi.w);
            }
        }

        // C build: one s per 64-pair chunk (64 | 768): float4 math, 1 STS.128.
        {
            const int s  = pair0 / D_MODEL;
            const int d0 = pair0 % D_MODEL;
            const int p  = threadIdx.x >> 2;
            const int rq = threadIdx.x & 3;
            const float4 m4 = *reinterpret_cast<const float4*>(&g_mod[s * RANK + rq * 4]);
            const float4 a4 = *reinterpret_cast<const float4*>(&A[(d0 + p) * RANK + rq * 4]);
            float4 c4;
            c4.x = m4.x * a4.x;  c4.y = m4.y * a4.y;
            c4.z = m4.z * a4.z;  c4.w = m4.w * a4.w;
            *reinterpret_cast<float4*>(&Cs[p][rq * 4]) = c4;
        }
        __syncthreads();

        float* outp = out + (size_t)pair0 * D_FFN + f0;
#pragma unroll 1
        for (int p = 0; p < CHUNK_PAIRS; p++) {
            // 4 LDS.128 -> 8 packed {c2j, c2j+1} operands, no duplication.
            const ulonglong2* cp = reinterpret_cast<const ulonglong2*>(&Cs[p][0]);
            uint64_t acc0 = 0ull, acc1 = 0ull, acc2 = 0ull, acc3 = 0ull;
#pragma unroll
            for (int i = 0; i < 4; i++) {
                const ulonglong2 cc = cp[i];   // {c4i,c4i+1}, {c4i+2,c4i+3}
                FMA_F32X2(acc0, cc.x, Bp[2 * i][0], acc0);
                FMA_F32X2(acc1, cc.x, Bp[2 * i][1], acc1);
                FMA_F32X2(acc2, cc.x, Bp[2 * i][2], acc2);
                FMA_F32X2(acc3, cc.x, Bp[2 * i][3], acc3);
                FMA_F32X2(acc0, cc.y, Bp[2 * i + 1][0], acc0);
                FMA_F32X2(acc1, cc.y, Bp[2 * i + 1][1], acc1);
                FMA_F32X2(acc2, cc.y, Bp[2 * i + 1][2], acc2);
                FMA_F32X2(acc3, cc.y, Bp[2 * i + 1][3], acc3);
            }
            // Horizontal: out[f] = even-r sum + odd-r sum (register halves).
            float4 v;
            v.x = __uint_as_float((uint32_t)(acc0 & 0xFFFFFFFFull)) +
                  __uint_as_float((uint32_t)(acc0 >> 32));
            v.y = __uint_as_float((uint32_t)(acc1 & 0xFFFFFFFFull)) +
                  __uint_as_float((uint32_t)(acc1 >> 32));
            v.z = __uint_as_float((uint32_t)(acc2 & 0xFFFFFFFFull)) +
                  __uint_as_float((uint32_t)(acc2 >> 32));
            v.w = __uint_as_float((uint32_t)(acc3 & 0xFFFFFFFFull)) +
                  __uint_as_float((uint32_t)(acc3 >> 32));
            __stcs(reinterpret_cast<float4*>(outp), v);   // streaming store
            outp += D_FFN;
        }

        if (threadIdx.x == 0) s_claim = next_claim;
        __syncthreads();
    }
}

// ---------------------------------------------------------------------------
// Launch
// ---------------------------------------------------------------------------
extern "C" void kernel_launch(void* const* d_in, const int* in_sizes, int n_in,
                              void* d_out, int out_size)
{
    const float* attn = (const float*)d_in[0];  // (1, 64, 768)
    const float* A    = (const float*)d_in[1];  // (768, 16)
    const float* B    = (const float*)d_in[2];  // (16, 3072)
    float* out        = (float*)d_out;          // (1, 64, 768, 3072)

    mod_kernel<<<128, 256>>>(attn, A);
    deltaw_kernel<<<GRID_BLOCKS, THREADS>>>(A, B, out);
}

// round 14
// speedup vs baseline: 1.6399x; 1.6399x over previous
#include <cuda_runtime.h>
#include <cstdint>

// Problem constants
#define S_LEN   64
#define D_MODEL 768
#define D_FFN   3072
#define RANK    16
#define MOD_SCALE 0.1f

// Packed f32x2 ops (ptxas won't auto-fuse from C++).
#define FMA_F32X2(d, a, b, c) \
    asm("fma.rn.f32x2 %0, %1, %2, %3;" : "=l"(d) : "l"(a), "l"(b), "l"(c))
// Duplicate a scalar float into a packed {s,s} 64-bit operand.
#define DUP_F32X2(d, s) \
    asm("mov.b64 %0, {%1, %1};" : "=l"(d) : "r"(__float_as_uint(s)))

// Scratch: modulation (64 x 16) + work-stealing counter. Device globals.
__device__ float    g_mod[S_LEN * RANK];
__device__ unsigned g_ctr;

// ---------------------------------------------------------------------------
// Kernel 1: modulation[s][r] = 0.1 * tanh( sum_d attn[s][d] * A[d][r] )
// Warp-per-output; also resets the work counter for the deltaw launch.
// ---------------------------------------------------------------------------
__global__ __launch_bounds__(256)
void mod_kernel(const float* __restrict__ attn,
                const float* __restrict__ A)
{
    if (blockIdx.x == 0 && threadIdx.x == 0) g_ctr = 0u;

    const int gw  = blockIdx.x * 8 + (threadIdx.x >> 5);  // 0..1023
    const int lid = threadIdx.x & 31;
    const int s   = gw >> 4;
    const int r   = gw & 15;

    const float* arow = attn + (size_t)s * D_MODEL;
    float acc = 0.0f;
#pragma unroll
    for (int k = 0; k < D_MODEL / 32; k++) {              // 24 iterations
        const int d = lid + 32 * k;
        acc += arow[d] * A[d * RANK + r];
    }
#pragma unroll
    for (int off = 16; off > 0; off >>= 1)
        acc += __shfl_down_sync(0xFFFFFFFFu, acc, off);

    if (lid == 0) g_mod[s * RANK + r] = MOD_SCALE * tanhf(acc);
}

// ---------------------------------------------------------------------------
// Kernel 2: delta_w[p][f] = sum_r C[p][r] * B[r][f]
//
// R9 core EXACTLY (non-dup C smem, mov.b64 dup, 2-chain packed FFMA2,
// B slab register-resident, persistent 444-block work-steal, claim-ahead)
// with two changes:
//  1. DEFAULT-policy STG.128 (no __stcs): let L2 write-back absorb store
//     bursts; dirty lines flush lazily, overlapping the next graph replay.
//  2. CHUNK_PAIRS 128 (128 | 768, one s per chunk): halves claims, C-builds
//     and barriers per output. C build = 2x STS.128 per thread.
// ---------------------------------------------------------------------------
#define FTILE        1024
#define CHUNK_PAIRS  128
#define THREADS      256
#define N_PCHUNK     ((S_LEN * D_MODEL) / CHUNK_PAIRS)    // 384
#define N_ITEMS      (N_PCHUNK * (D_FFN / FTILE))         // 1152
#define GRID_BLOCKS  444

__global__ __launch_bounds__(THREADS, 3)
void deltaw_kernel(const float* __restrict__ A,
                   const float* __restrict__ B,
                   float* __restrict__ out)
{
    __shared__ __align__(16) float Cs[CHUNK_PAIRS][RANK];
    __shared__ unsigned s_claim;

    ulonglong2 Breg[RANK];
    int prev_ftile = -1;

    if (threadIdx.x == 0) s_claim = atomicAdd(&g_ctr, 1u);
    __syncthreads();

    for (;;) {
        const unsigned idx = s_claim;
        if (idx >= N_ITEMS) break;

        // Claim-ahead: issue next atomic now, publish after compute.
        unsigned next_claim = 0u;
        if (threadIdx.x == 0) next_claim = atomicAdd(&g_ctr, 1u);

        const int ftile = (int)(idx / N_PCHUNK);          // 0..2
        const int pair0 = (int)(idx % N_PCHUNK) * CHUNK_PAIRS;
        const int f0    = ftile * FTILE + threadIdx.x * 4;

        if (ftile != prev_ftile) {
            prev_ftile = ftile;
#pragma unroll
            for (int r = 0; r < RANK; r++) {
                Breg[r] = *reinterpret_cast<const ulonglong2*>(&B[r * D_FFN + f0]);
            }
        }

        // C build: one s per 128-pair chunk (128 | 768). Each thread builds
        // two (pair, r-quad) entries with float4 math, 2x STS.128.
        {
            const int s  = pair0 / D_MODEL;
            const int d0 = pair0 % D_MODEL;
#pragma unroll
            for (int h = 0; h < 2; h++) {
                const int e  = threadIdx.x + h * THREADS;   // 0..511
                const int p  = e >> 2;
                const int rq = e & 3;
                const float4 m4 = *reinterpret_cast<const float4*>(&g_mod[s * RANK + rq * 4]);
                const float4 a4 = *reinterpret_cast<const float4*>(&A[(d0 + p) * RANK + rq * 4]);
                float4 c4;
                c4.x = m4.x * a4.x;  c4.y = m4.y * a4.y;
                c4.z = m4.z * a4.z;  c4.w = m4.w * a4.w;
                *reinterpret_cast<float4*>(&Cs[p][rq * 4]) = c4;
            }
        }
        __syncthreads();

        float* outp = out + (size_t)pair0 * D_FFN + f0;
#pragma unroll 1
        for (int p = 0; p < CHUNK_PAIRS; p++) {
            const float4* cp = reinterpret_cast<const float4*>(&Cs[p][0]);
            uint64_t a0 = 0ull;   // packed accum for {f0, f0+1}
            uint64_t a1 = 0ull;   // packed accum for {f0+2, f0+3}
#pragma unroll
            for (int i = 0; i < 4; i++) {
                const float4 c4 = cp[i];      // one broadcast LDS.128
                uint64_t d0, d1, d2, d3;
                DUP_F32X2(d0, c4.x);
                DUP_F32X2(d1, c4.y);
                DUP_F32X2(d2, c4.z);
                DUP_F32X2(d3, c4.w);
                FMA_F32X2(a0, d0, Breg[4 * i + 0].x, a0);
                FMA_F32X2(a1, d0, Breg[4 * i + 0].y, a1);
                FMA_F32X2(a0, d1, Breg[4 * i + 1].x, a0);
                FMA_F32X2(a1, d1, Breg[4 * i + 1].y, a1);
                FMA_F32X2(a0, d2, Breg[4 * i + 2].x, a0);
                FMA_F32X2(a1, d2, Breg[4 * i + 2].y, a1);
                FMA_F32X2(a0, d3, Breg[4 * i + 3].x, a0);
                FMA_F32X2(a1, d3, Breg[4 * i + 3].y, a1);
            }
            float4 v;
            v.x = __uint_as_float((uint32_t)(a0 & 0xFFFFFFFFull));
            v.y = __uint_as_float((uint32_t)(a0 >> 32));
            v.z = __uint_as_float((uint32_t)(a1 & 0xFFFFFFFFull));
            v.w = __uint_as_float((uint32_t)(a1 >> 32));
            *reinterpret_cast<float4*>(outp) = v;   // default-policy STG.128
            outp += D_FFN;
        }

        if (threadIdx.x == 0) s_claim = next_claim;
        __syncthreads();
    }
}

// ---------------------------------------------------------------------------
// Launch
// ---------------------------------------------------------------------------
extern "C" void kernel_launch(void* const* d_in, const int* in_sizes, int n_in,
                              void* d_out, int out_size)
{
    const float* attn = (const float*)d_in[0];  // (1, 64, 768)
    const float* A    = (const float*)d_in[1];  // (768, 16)
    const float* B    = (const float*)d_in[2];  // (16, 3072)
    float* out        = (float*)d_out;          // (1, 64, 768, 3072)

    mod_kernel<<<128, 256>>>(attn, A);
    deltaw_kernel<<<GRID_BLOCKS, THREADS>>>(A, B, out);
}

// round 15
// speedup vs baseline: 1.7317x; 1.0560x over previous
#include <cuda_runtime.h>
#include <cstdint>

// Problem constants
#define S_LEN   64
#define D_MODEL 768
#define D_FFN   3072
#define RANK    16
#define MOD_SCALE 0.1f

// Packed f32x2 ops (ptxas won't auto-fuse from C++).
#define FMA_F32X2(d, a, b, c) \
    asm("fma.rn.f32x2 %0, %1, %2, %3;" : "=l"(d) : "l"(a), "l"(b), "l"(c))
// Duplicate a scalar float into a packed {s,s} 64-bit operand.
#define DUP_F32X2(d, s) \
    asm("mov.b64 %0, {%1, %1};" : "=l"(d) : "r"(__float_as_uint(s)))

// Scratch: modulation (64 x 16) + work-stealing counter. Device globals.
__device__ float    g_mod[S_LEN * RANK];
__device__ unsigned g_ctr;

// ---------------------------------------------------------------------------
// Kernel 1: modulation[s][r] = 0.1 * tanh( sum_d attn[s][d] * A[d][r] )
// Warp-per-output; also resets the work counter for the deltaw launch.
// ---------------------------------------------------------------------------
__global__ __launch_bounds__(256)
void mod_kernel(const float* __restrict__ attn,
                const float* __restrict__ A)
{
    if (blockIdx.x == 0 && threadIdx.x == 0) g_ctr = 0u;

    const int gw  = blockIdx.x * 8 + (threadIdx.x >> 5);  // 0..1023
    const int lid = threadIdx.x & 31;
    const int s   = gw >> 4;
    const int r   = gw & 15;

    const float* arow = attn + (size_t)s * D_MODEL;
    float acc = 0.0f;
#pragma unroll
    for (int k = 0; k < D_MODEL / 32; k++) {              // 24 iterations
        const int d = lid + 32 * k;
        acc += arow[d] * A[d * RANK + r];
    }
#pragma unroll
    for (int off = 16; off > 0; off >>= 1)
        acc += __shfl_down_sync(0xFFFFFFFFu, acc, off);

    if (lid == 0) g_mod[s * RANK + r] = MOD_SCALE * tanhf(acc);
}

// ---------------------------------------------------------------------------
// Kernel 2: delta_w[p][f] = sum_r C[p][r] * B[r][f],  p = s*768 + d,
//           C[p][r] = mod[s][r] * A[d][r]
//
// R9 configuration VERBATIM (the 99.4us best: persistent 444 blocks,
// claim-ahead work-steal, CHUNK 64, non-dup C smem, mov.b64 dup, 2-chain
// packed FFMA2, B slab register-resident) with exactly ONE change:
// default-policy STG.128 instead of __stcs, letting L2 write-back defer
// part of the 604MB store stream past kernel end (flushes overlap the next
// graph replay's compute ramp instead of throttling this kernel).
// ---------------------------------------------------------------------------
#define FTILE        1024
#define PAIRS_PER_CH 64
#define THREADS      256
#define N_PCHUNK     ((S_LEN * D_MODEL) / PAIRS_PER_CH)   // 768
#define N_ITEMS      (N_PCHUNK * (D_FFN / FTILE))         // 2304
#define GRID_BLOCKS  444

__global__ __launch_bounds__(THREADS, 3)
void deltaw_kernel(const float* __restrict__ A,
                   const float* __restrict__ B,
                   float* __restrict__ out)
{
    __shared__ float    Cs[PAIRS_PER_CH][RANK];
    __shared__ unsigned s_claim;

    ulonglong2 Breg[RANK];
    int prev_ftile = -1;

    // Prologue: claim the first work item.
    if (threadIdx.x == 0) s_claim = atomicAdd(&g_ctr, 1u);
    __syncthreads();

    for (;;) {
        const unsigned idx = s_claim;
        if (idx >= N_ITEMS) break;

        // Claim-ahead: start the next atomic now; publish after compute.
        unsigned next_claim = 0u;
        if (threadIdx.x == 0) next_claim = atomicAdd(&g_ctr, 1u);

        const int ftile = (int)(idx / N_PCHUNK);          // 0..2
        const int pair0 = (int)(idx % N_PCHUNK) * PAIRS_PER_CH;
        const int f0    = ftile * FTILE + threadIdx.x * 4;

        // Reload B slab only when the f-tile changes.
        if (ftile != prev_ftile) {
            prev_ftile = ftile;
#pragma unroll
            for (int r = 0; r < RANK; r++) {
                Breg[r] = *reinterpret_cast<const ulonglong2*>(&B[r * D_FFN + f0]);
            }
        }

        // Build C (non-duplicated) for this chunk.
        for (int i = threadIdx.x; i < PAIRS_PER_CH * RANK; i += THREADS) {
            const int p  = i >> 4;
            const int r  = i & 15;
            const int pd = pair0 + p;
            const int s  = pd / D_MODEL;
            const int d  = pd % D_MODEL;
            Cs[p][r] = g_mod[s * RANK + r] * A[d * RANK + r];
        }
        __syncthreads();

        float* outp = out + (size_t)pair0 * D_FFN + f0;
#pragma unroll 1
        for (int p = 0; p < PAIRS_PER_CH; p++) {
            const float4* cp = reinterpret_cast<const float4*>(&Cs[p][0]);
            uint64_t a0 = 0ull;   // packed accum for {f0, f0+1}
            uint64_t a1 = 0ull;   // packed accum for {f0+2, f0+3}
#pragma unroll
            for (int i = 0; i < 4; i++) {
                const float4 c4 = cp[i];      // one broadcast LDS.128
                uint64_t d0, d1, d2, d3;
                DUP_F32X2(d0, c4.x);
                DUP_F32X2(d1, c4.y);
                DUP_F32X2(d2, c4.z);
                DUP_F32X2(d3, c4.w);
                FMA_F32X2(a0, d0, Breg[4 * i + 0].x, a0);
                FMA_F32X2(a1, d0, Breg[4 * i + 0].y, a1);
                FMA_F32X2(a0, d1, Breg[4 * i + 1].x, a0);
                FMA_F32X2(a1, d1, Breg[4 * i + 1].y, a1);
                FMA_F32X2(a0, d2, Breg[4 * i + 2].x, a0);
                FMA_F32X2(a1, d2, Breg[4 * i + 2].y, a1);
                FMA_F32X2(a0, d3, Breg[4 * i + 3].x, a0);
                FMA_F32X2(a1, d3, Breg[4 * i + 3].y, a1);
            }
            float4 v;
            v.x = __uint_as_float((uint32_t)(a0 & 0xFFFFFFFFull));
            v.y = __uint_as_float((uint32_t)(a0 >> 32));
            v.z = __uint_as_float((uint32_t)(a1 & 0xFFFFFFFFull));
            v.w = __uint_as_float((uint32_t)(a1 >> 32));
            *reinterpret_cast<float4*>(outp) = v;   // default-policy STG.128
            outp += D_FFN;
        }

        // Publish the prefetched claim; barrier orders it and the Cs reuse.
        if (threadIdx.x == 0) s_claim = next_claim;
        __syncthreads();
    }
}

// ---------------------------------------------------------------------------
// Launch
// ---------------------------------------------------------------------------
extern "C" void kernel_launch(void* const* d_in, const int* in_sizes, int n_in,
                              void* d_out, int out_size)
{
    const float* attn = (const float*)d_in[0];  // (1, 64, 768)
    const float* A    = (const float*)d_in[1];  // (768, 16)
    const float* B    = (const float*)d_in[2];  // (16, 3072)
    float* out        = (float*)d_out;          // (1, 64, 768, 3072)

    mod_kernel<<<128, 256>>>(attn, A);
    deltaw_kernel<<<GRID_BLOCKS, THREADS>>>(A, B, out);
}